// round 2
// baseline (speedup 1.0000x reference)
#include <cuda_runtime.h>
#include <cstdint>

#define B_ 1024
#define T_ 256
#define D_ 64
#define H_ 128
#define RROWS 4

// Scratch for precomputed x-projections (pre-activation, bias included).
__device__ float g_xg[(size_t)B_ * T_ * 256];   // gate: r cols 0..127, u cols 128..255
__device__ float g_xc[(size_t)B_ * T_ * 128];   // candidate

// ---- packed f32x2 helpers (ptxas won't auto-fuse; must be PTX) ----
__device__ __forceinline__ unsigned long long pack2(float lo, float hi) {
    unsigned long long r;
    asm("mov.b64 %0, {%1, %2};" : "=l"(r) : "f"(lo), "f"(hi));
    return r;
}
__device__ __forceinline__ void fma2(unsigned long long& acc,
                                     unsigned long long a,
                                     unsigned long long b) {
    asm("fma.rn.f32x2 %0, %1, %2, %0;" : "+l"(acc) : "l"(a), "l"(b));
}
__device__ __forceinline__ float sum2(unsigned long long a) {
    float lo, hi;
    asm("mov.b64 {%0, %1}, %2;" : "=f"(lo), "=f"(hi) : "l"(a));
    return lo + hi;
}

// ============================================================================
// Phase A: time-parallel x-projections. Weights in regs, x via LDS.128.
// ============================================================================
__global__ __launch_bounds__(384)
void gru_phaseA(const int* __restrict__ item_his,
                const int* __restrict__ seq_lens,
                const float* __restrict__ emb,
                const float* __restrict__ Wg,
                const float* __restrict__ bg,
                const float* __restrict__ Wc,
                const float* __restrict__ bc)
{
    const int b  = blockIdx.y;
    const int t0 = blockIdx.x * 64;
    const int len = seq_lens[b];
    if (t0 >= len) return;
    const int nt = min(64, len - t0);
    const int tid = threadIdx.x;

    __shared__ int idx_sh[64];
    __shared__ __align__(16) float x_sh[64 * 64];   // [row][k]

    unsigned long long wp[32];
    float bias;
    if (tid < 256) {
        bias = bg[tid];
#pragma unroll
        for (int i = 0; i < 32; i++)
            wp[i] = pack2(Wg[(2 * i) * 256 + tid], Wg[(2 * i + 1) * 256 + tid]);
    } else {
        const int c = tid - 256;
        bias = bc[c];
#pragma unroll
        for (int i = 0; i < 32; i++)
            wp[i] = pack2(Wc[(2 * i) * 128 + c], Wc[(2 * i + 1) * 128 + c]);
    }

    if (tid < nt) idx_sh[tid] = item_his[b * T_ + t0 + tid];
    __syncthreads();

    {   // coalesced gather: nt embedding rows of 256B each
        const float4* e4 = (const float4*)emb;
        float4* x4 = (float4*)x_sh;
        for (int i = tid; i < nt * 16; i += 384) {
            const int r = i >> 4, q = i & 15;
            x4[r * 16 + q] = e4[(size_t)idx_sh[r] * 16 + q];
        }
    }
    __syncthreads();

    const ulonglong2* x2 = (const ulonglong2*)x_sh;   // 16 × 16B per row
    for (int r = 0; r < nt; r++) {
        unsigned long long a0 = 0ULL, a1 = 0ULL;
#pragma unroll 8
        for (int i = 0; i < 16; i++) {
            ulonglong2 xx = x2[r * 16 + i];           // LDS.128 broadcast
            fma2(a0, xx.x, wp[2 * i]);
            fma2(a1, xx.y, wp[2 * i + 1]);
        }
        const float acc = sum2(a0) + sum2(a1) + bias;
        const size_t p = (size_t)b * T_ + t0 + r;
        if (tid < 256) g_xg[p * 256 + tid] = acc;
        else           g_xc[p * 128 + (tid - 256)] = acc;
    }
}

// ============================================================================
// Phase B: recurrence. R=4 rows/CTA, SMEM weights (stride 132, conflict-free
// LDS.128), double-buffered h, 2 barriers/step, x-proj prefetch.
// SMEM layout (floats):
//   wg  [256][132] @ 0        (33792)
//   wc  [128][132] @ 33792    (16896)
//   h   [2][4][128] @ 50688   (1024)
//   rh  [4][128]   @ 51712    (512)
//   u   [4][128]   @ 52224    (512)   total 52736 floats = 210944 B
// ============================================================================
#define SMEM_B_FLOATS 52736
#define OFF_WC 33792
#define OFF_H  50688
#define OFF_RH 51712
#define OFF_U  52224

template<int NA>
__device__ __forceinline__ void gate_step(const ulonglong2* __restrict__ w2,
                                          const float* __restrict__ hcur,
                                          float* __restrict__ rh,
                                          float* __restrict__ uu,
                                          const float* __restrict__ xv, int j)
{
    unsigned long long a0[NA], a1[NA];
#pragma unroll
    for (int r = 0; r < NA; r++) { a0[r] = 0ULL; a1[r] = 0ULL; }
#pragma unroll 8
    for (int kk = 0; kk < 32; kk++) {
        ulonglong2 w = w2[kk];                         // LDS.128, conflict-free
#pragma unroll
        for (int r = 0; r < NA; r++) {
            ulonglong2 hv = ((const ulonglong2*)(hcur + r * 128))[kk];  // broadcast
            fma2(a0[r], hv.x, w.x);
            fma2(a1[r], hv.y, w.y);
        }
    }
#pragma unroll
    for (int r = 0; r < NA; r++) {
        const float s = sum2(a0[r]) + sum2(a1[r]) + xv[r];
        const float g = 1.f / (1.f + __expf(-s));
        if (j < 128) rh[r * 128 + j] = g * hcur[r * 128 + j];   // r-gate * h
        else         uu[r * 128 + (j - 128)] = g;               // u-gate
    }
}

template<int NA>
__device__ __forceinline__ void cand_step(const ulonglong2* __restrict__ w2,
                                          const float* __restrict__ rh,
                                          const float* __restrict__ uu,
                                          const float* __restrict__ hcur,
                                          float* __restrict__ hnxt,
                                          const float* __restrict__ xv, int j)
{
    unsigned long long a0[NA], a1[NA];
#pragma unroll
    for (int r = 0; r < NA; r++) { a0[r] = 0ULL; a1[r] = 0ULL; }
#pragma unroll 8
    for (int kk = 0; kk < 32; kk++) {
        ulonglong2 w = w2[kk];
#pragma unroll
        for (int r = 0; r < NA; r++) {
            ulonglong2 hv = ((const ulonglong2*)(rh + r * 128))[kk];
            fma2(a0[r], hv.x, w.x);
            fma2(a1[r], hv.y, w.y);
        }
    }
#pragma unroll
    for (int r = 0; r < NA; r++) {
        const float s  = sum2(a0[r]) + sum2(a1[r]) + xv[r];
        const float sc = fminf(fmaxf(s, -15.f), 15.f);
        const float e  = __expf(2.f * sc);
        const float c  = (e - 1.f) / (e + 1.f);       // tanh, overflow-safe
        const float u  = uu[r * 128 + j];
        hnxt[r * 128 + j] = u * hcur[r * 128 + j] + (1.f - u) * c;
    }
}

__global__ __launch_bounds__(384, 1)
void gru_phaseB(const int* __restrict__ seq_lens,
                const float* __restrict__ Wg,
                const float* __restrict__ Wc,
                float* __restrict__ out)
{
    extern __shared__ float sh[];
    float* wg   = sh;
    float* wc   = sh + OFF_WC;
    float* hbuf = sh + OFF_H;
    float* rh   = sh + OFF_RH;
    float* uu   = sh + OFF_U;

    const int tid = threadIdx.x;
    const int c   = blockIdx.x;

    // Load recurrent weights transposed: [col][k], padded stride 132.
    for (int i = tid; i < 256 * 128; i += 384) {
        const int k = i >> 8, col = i & 255;
        wg[col * 132 + k] = Wg[(64 + k) * 256 + col];
    }
    for (int i = tid; i < 128 * 128; i += 384) {
        const int k = i >> 7, col = i & 127;
        wc[col * 132 + k] = Wc[(64 + k) * 128 + col];
    }
    for (int i = tid; i < 1024; i += 384) hbuf[i] = 0.f;

    // This CTA's 4 rows, sorted by len descending (active set = prefix).
    int bidx[RROWS], len[RROWS];
#pragma unroll
    for (int r = 0; r < RROWS; r++) { bidx[r] = c + 256 * r; len[r] = seq_lens[bidx[r]]; }
#define CSWAP(a,b) if (len[a] < len[b]) { int tl=len[a];len[a]=len[b];len[b]=tl; \
                                          int tb=bidx[a];bidx[a]=bidx[b];bidx[b]=tb; }
    CSWAP(0,1) CSWAP(2,3) CSWAP(0,2) CSWAP(1,3) CSWAP(1,2)
#undef CSWAP
    const int maxlen = len[0];

    const bool isGate = tid < 256;
    const int  j      = isGate ? tid : tid - 256;
    const ulonglong2* w2 = (const ulonglong2*)((isGate ? wg : wc) + j * 132);

    __syncthreads();

    float xv[RROWS], xn[RROWS];
#pragma unroll
    for (int r = 0; r < RROWS; r++)
        xv[r] = (0 < len[r])
              ? (isGate ? g_xg[((size_t)bidx[r] * T_) * 256 + j]
                        : g_xc[((size_t)bidx[r] * T_) * 128 + j]) : 0.f;

    int cur = 0;
    for (int t = 0; t < maxlen; t++) {
        const int na = (t < len[3]) ? 4 : (t < len[2]) ? 3 : (t < len[1]) ? 2 : 1;

        // prefetch next step's x-projections (consumed next iteration)
#pragma unroll
        for (int r = 0; r < RROWS; r++)
            xn[r] = (t + 1 < len[r])
                  ? (isGate ? g_xg[((size_t)bidx[r] * T_ + t + 1) * 256 + j]
                            : g_xc[((size_t)bidx[r] * T_ + t + 1) * 128 + j]) : 0.f;

        const float* hcur = hbuf + cur * 512;
        float*       hnxt = hbuf + (cur ^ 1) * 512;

        if (isGate) {
            switch (na) {
                case 4: gate_step<4>(w2, hcur, rh, uu, xv, j); break;
                case 3: gate_step<3>(w2, hcur, rh, uu, xv, j); break;
                case 2: gate_step<2>(w2, hcur, rh, uu, xv, j); break;
                default: gate_step<1>(w2, hcur, rh, uu, xv, j); break;
            }
        }
        __syncthreads();
        if (!isGate) {
            switch (na) {
                case 4: cand_step<4>(w2, rh, uu, hcur, hnxt, xv, j); break;
                case 3: cand_step<3>(w2, rh, uu, hcur, hnxt, xv, j); break;
                case 2: cand_step<2>(w2, rh, uu, hcur, hnxt, xv, j); break;
                default: cand_step<1>(w2, rh, uu, hcur, hnxt, xv, j); break;
            }
            for (int r = na; r < RROWS; r++)              // copy-through dead rows
                hnxt[r * 128 + j] = hcur[r * 128 + j];
        }
        __syncthreads();
        cur ^= 1;
#pragma unroll
        for (int r = 0; r < RROWS; r++) xv[r] = xn[r];
    }

    for (int i = tid; i < RROWS * 128; i += 384) {
        const int r = i >> 7, jj = i & 127;
        out[bidx[r] * 128 + jj] = hbuf[cur * 512 + r * 128 + jj];
    }
}

// ============================================================================
extern "C" void kernel_launch(void* const* d_in, const int* in_sizes, int n_in,
                              void* d_out, int out_size)
{
    const int*   item_his = (const int*)d_in[0];
    const int*   seq_lens = (const int*)d_in[1];
    const float* emb      = (const float*)d_in[2];
    const float* Wg       = (const float*)d_in[3];
    const float* bg       = (const float*)d_in[4];
    const float* Wc       = (const float*)d_in[5];
    const float* bc       = (const float*)d_in[6];
    float* out = (float*)d_out;

    cudaFuncSetAttribute(gru_phaseB, cudaFuncAttributeMaxDynamicSharedMemorySize,
                         SMEM_B_FLOATS * 4);

    dim3 gA(T_ / 64, B_);   // (4, 1024)
    gru_phaseA<<<gA, 384>>>(item_his, seq_lens, emb, Wg, bg, Wc, bc);
    gru_phaseB<<<B_ / RROWS, 384, SMEM_B_FLOATS * 4>>>(seq_lens, Wg, Wc, out);
}

// round 3
// speedup vs baseline: 1.5232x; 1.5232x over previous
#include <cuda_runtime.h>
#include <cstdint>

#define B_ 1024
#define T_ 256
#define D_ 64
#define H_ 128

// Precomputed x-projections (pre-activation, bias included).
__device__ float g_xg[(size_t)B_ * T_ * 256];   // gate: r cols 0..127, u cols 128..255
__device__ float g_xc[(size_t)B_ * T_ * 128];   // candidate

// ---- packed f32x2 helpers ----
__device__ __forceinline__ unsigned long long pack2(float lo, float hi) {
    unsigned long long r;
    asm("mov.b64 %0, {%1, %2};" : "=l"(r) : "f"(lo), "f"(hi));
    return r;
}
__device__ __forceinline__ void fma2(unsigned long long& acc,
                                     unsigned long long a,
                                     unsigned long long b) {
    asm("fma.rn.f32x2 %0, %1, %2, %0;" : "+l"(acc) : "l"(a), "l"(b));
}
__device__ __forceinline__ float sum2(unsigned long long a) {
    float lo, hi;
    asm("mov.b64 {%0, %1}, %2;" : "=f"(lo), "=f"(hi) : "l"(a));
    return lo + hi;
}
__device__ __forceinline__ float sigmoidf(float s) {
    return 1.f / (1.f + __expf(-s));
}
__device__ __forceinline__ float tanh_safe(float s) {
    const float sc = fminf(fmaxf(s, -15.f), 15.f);
    const float e  = __expf(2.f * sc);
    return (e - 1.f) / (e + 1.f);
}

// ============================================================================
// Phase A: time-parallel x-projections. Weights in regs, x via LDS.128.
// ============================================================================
__global__ __launch_bounds__(384)
void gru_phaseA(const int* __restrict__ item_his,
                const int* __restrict__ seq_lens,
                const float* __restrict__ emb,
                const float* __restrict__ Wg,
                const float* __restrict__ bg,
                const float* __restrict__ Wc,
                const float* __restrict__ bc)
{
    const int b  = blockIdx.y;
    const int t0 = blockIdx.x * 64;
    const int len = seq_lens[b];
    if (t0 >= len) return;
    const int nt = min(64, len - t0);
    const int tid = threadIdx.x;

    __shared__ int idx_sh[64];
    __shared__ __align__(16) float x_sh[64 * 64];

    unsigned long long wp[32];
    float bias;
    if (tid < 256) {
        bias = bg[tid];
#pragma unroll
        for (int i = 0; i < 32; i++)
            wp[i] = pack2(Wg[(2 * i) * 256 + tid], Wg[(2 * i + 1) * 256 + tid]);
    } else {
        const int c = tid - 256;
        bias = bc[c];
#pragma unroll
        for (int i = 0; i < 32; i++)
            wp[i] = pack2(Wc[(2 * i) * 128 + c], Wc[(2 * i + 1) * 128 + c]);
    }

    if (tid < nt) idx_sh[tid] = item_his[b * T_ + t0 + tid];
    __syncthreads();

    {   // coalesced gather: nt embedding rows of 256B each
        const float4* e4 = (const float4*)emb;
        float4* x4 = (float4*)x_sh;
        for (int i = tid; i < nt * 16; i += 384) {
            const int r = i >> 4, q = i & 15;
            x4[r * 16 + q] = e4[(size_t)idx_sh[r] * 16 + q];
        }
    }
    __syncthreads();

    const ulonglong2* x2 = (const ulonglong2*)x_sh;
    for (int r = 0; r < nt; r++) {
        unsigned long long a0 = 0ULL, a1 = 0ULL;
#pragma unroll
        for (int i = 0; i < 16; i++) {
            ulonglong2 xx = x2[r * 16 + i];           // LDS.128 broadcast
            fma2(a0, xx.x, wp[2 * i]);
            fma2(a1, xx.y, wp[2 * i + 1]);
        }
        const float acc = sum2(a0) + sum2(a1) + bias;
        const size_t p = (size_t)b * T_ + t0 + r;
        if (tid < 256) g_xg[p * 256 + tid] = acc;
        else           g_xc[p * 128 + (tid - 256)] = acc;
    }
}

// ============================================================================
// Phase B: pipelined recurrence.
//   4 rows/CTA sorted desc; groups A = {s0,s3}, B = {s1,s2}.
//   slot0: gate-warps do gates_A(t)   | cand-warps do cand_B(t-1)
//   slot1: gate-warps do gates_B(t)   | cand-warps do cand_A(t)
//   Weights register-resident (64 b64/thread); h/rh broadcast LDS.128.
// ============================================================================
template<int NR>
__device__ __forceinline__ void dot2(const unsigned long long* __restrict__ wp,
                                     const float* __restrict__ v0,
                                     const float* __restrict__ v1,
                                     float& s0, float& s1)
{
    const ulonglong2* p0 = (const ulonglong2*)v0;
    const ulonglong2* p1 = (const ulonglong2*)v1;
    unsigned long long a00 = 0ULL, a01 = 0ULL, a10 = 0ULL, a11 = 0ULL;
#pragma unroll
    for (int kk = 0; kk < 32; kk++) {
        ulonglong2 x0 = p0[kk];                       // LDS.128 broadcast
        fma2(a00, x0.x, wp[2 * kk]);
        fma2(a01, x0.y, wp[2 * kk + 1]);
        if (NR == 2) {
            ulonglong2 x1 = p1[kk];
            fma2(a10, x1.x, wp[2 * kk]);
            fma2(a11, x1.y, wp[2 * kk + 1]);
        }
    }
    s0 = sum2(a00) + sum2(a01);
    if (NR == 2) s1 = sum2(a10) + sum2(a11);
}

__global__ __launch_bounds__(384, 1)
void gru_phaseB(const int* __restrict__ seq_lens,
                const float* __restrict__ Wg,
                const float* __restrict__ Wc,
                float* __restrict__ out)
{
    __shared__ __align__(16) float h[4][128];
    __shared__ __align__(16) float rh[4][128];
    __shared__ float uu[4][128];

    const int tid = threadIdx.x;
    const int cta = blockIdx.x;

    // 4 rows sorted by len desc
    int bidx[4], len[4];
#pragma unroll
    for (int r = 0; r < 4; r++) { bidx[r] = cta + 256 * r; len[r] = seq_lens[bidx[r]]; }
#define CSWAP(a,b) if (len[a] < len[b]) { int tl=len[a];len[a]=len[b];len[b]=tl; \
                                          int tb=bidx[a];bidx[a]=bidx[b];bidx[b]=tb; }
    CSWAP(0,1) CSWAP(2,3) CSWAP(0,2) CSWAP(1,3) CSWAP(1,2)
#undef CSWAP
    // groups: A = rows {0,3}, B = {1,2} (balanced pairing)
    const int lA0 = len[0], lA1 = len[3], lB0 = len[1], lB1 = len[2];
    const int bA0 = bidx[0], bA1 = bidx[3], bB0 = bidx[1], bB1 = bidx[2];
    const int tmax = lA0;

    const bool isGate = tid < 256;
    const int  j      = isGate ? tid : tid - 256;

    // register-resident recurrent weight column
    unsigned long long wp[64];
    if (isGate) {
#pragma unroll
        for (int i = 0; i < 64; i++)
            wp[i] = pack2(Wg[(64 + 2 * i) * 256 + j], Wg[(64 + 2 * i + 1) * 256 + j]);
    } else {
#pragma unroll
        for (int i = 0; i < 64; i++)
            wp[i] = pack2(Wc[(64 + 2 * i) * 128 + j], Wc[(64 + 2 * i + 1) * 128 + j]);
    }

    for (int i = tid; i < 512; i += 384) ((float*)h)[i] = 0.f;
    __syncthreads();

    // x-projection prefetch registers
    float xgA0 = 0.f, xgA1 = 0.f, xgB0 = 0.f, xgB1 = 0.f;   // gate threads, step t
    float xcA0 = 0.f, xcA1 = 0.f;                           // cand threads, xc_A(t)
    float xcB0 = 0.f, xcB1 = 0.f;                           // cand threads, xc_B(t-1)
    if (isGate) {
        if (0 < lA0) xgA0 = g_xg[((size_t)bA0 * T_) * 256 + j];
        if (0 < lA1) xgA1 = g_xg[((size_t)bA1 * T_) * 256 + j];
        if (0 < lB0) xgB0 = g_xg[((size_t)bB0 * T_) * 256 + j];
        if (0 < lB1) xgB1 = g_xg[((size_t)bB1 * T_) * 256 + j];
    } else {
        if (0 < lA0) xcA0 = g_xc[((size_t)bA0 * T_) * 128 + j];
        if (0 < lA1) xcA1 = g_xc[((size_t)bA1 * T_) * 128 + j];
    }

    for (int t = 0; t <= tmax; t++) {
        // ---- prefetch for next iteration ----
        float nxgA0 = 0.f, nxgA1 = 0.f, nxgB0 = 0.f, nxgB1 = 0.f;
        float nxcA0 = 0.f, nxcA1 = 0.f, nxcB0 = 0.f, nxcB1 = 0.f;
        if (isGate) {
            if (t + 1 < lA0) nxgA0 = g_xg[((size_t)bA0 * T_ + t + 1) * 256 + j];
            if (t + 1 < lA1) nxgA1 = g_xg[((size_t)bA1 * T_ + t + 1) * 256 + j];
            if (t + 1 < lB0) nxgB0 = g_xg[((size_t)bB0 * T_ + t + 1) * 256 + j];
            if (t + 1 < lB1) nxgB1 = g_xg[((size_t)bB1 * T_ + t + 1) * 256 + j];
        } else {
            if (t + 1 < lA0) nxcA0 = g_xc[((size_t)bA0 * T_ + t + 1) * 128 + j];
            if (t + 1 < lA1) nxcA1 = g_xc[((size_t)bA1 * T_ + t + 1) * 128 + j];
            if (t     < lB0) nxcB0 = g_xc[((size_t)bB0 * T_ + t) * 128 + j];
            if (t     < lB1) nxcB1 = g_xc[((size_t)bB1 * T_ + t) * 128 + j];
        }

        // ---- slot 0: gates_A(t) | cand_B(t-1) ----
        if (isGate) {
            if (t < lA0) {
                float s0, s1;
                if (t < lA1) dot2<2>(wp, h[0], h[3], s0, s1);
                else         dot2<1>(wp, h[0], h[3], s0, s1);
                const float g0 = sigmoidf(s0 + xgA0);
                if (j < 128) rh[0][j] = g0 * h[0][j]; else uu[0][j - 128] = g0;
                if (t < lA1) {
                    const float g1 = sigmoidf(s1 + xgA1);
                    if (j < 128) rh[3][j] = g1 * h[3][j]; else uu[3][j - 128] = g1;
                }
            }
        } else {
            const int tt = t - 1;
            if (tt >= 0 && tt < lB0) {
                float s0, s1;
                if (tt < lB1) dot2<2>(wp, rh[1], rh[2], s0, s1);
                else          dot2<1>(wp, rh[1], rh[2], s0, s1);
                const float c0 = tanh_safe(s0 + xcB0);
                const float u0 = uu[1][j];
                h[1][j] = u0 * h[1][j] + (1.f - u0) * c0;
                if (tt < lB1) {
                    const float c1 = tanh_safe(s1 + xcB1);
                    const float u1 = uu[2][j];
                    h[2][j] = u1 * h[2][j] + (1.f - u1) * c1;
                }
            }
        }
        __syncthreads();

        // ---- slot 1: gates_B(t) | cand_A(t) ----
        if (isGate) {
            if (t < lB0) {
                float s0, s1;
                if (t < lB1) dot2<2>(wp, h[1], h[2], s0, s1);
                else         dot2<1>(wp, h[1], h[2], s0, s1);
                const float g0 = sigmoidf(s0 + xgB0);
                if (j < 128) rh[1][j] = g0 * h[1][j]; else uu[1][j - 128] = g0;
                if (t < lB1) {
                    const float g1 = sigmoidf(s1 + xgB1);
                    if (j < 128) rh[2][j] = g1 * h[2][j]; else uu[2][j - 128] = g1;
                }
            }
        } else {
            if (t < lA0) {
                float s0, s1;
                if (t < lA1) dot2<2>(wp, rh[0], rh[3], s0, s1);
                else         dot2<1>(wp, rh[0], rh[3], s0, s1);
                const float c0 = tanh_safe(s0 + xcA0);
                const float u0 = uu[0][j];
                h[0][j] = u0 * h[0][j] + (1.f - u0) * c0;
                if (t < lA1) {
                    const float c1 = tanh_safe(s1 + xcA1);
                    const float u1 = uu[3][j];
                    h[3][j] = u1 * h[3][j] + (1.f - u1) * c1;
                }
            }
        }
        __syncthreads();

        xgA0 = nxgA0; xgA1 = nxgA1; xgB0 = nxgB0; xgB1 = nxgB1;
        xcA0 = nxcA0; xcA1 = nxcA1; xcB0 = nxcB0; xcB1 = nxcB1;
    }

    for (int i = tid; i < 512; i += 384)
        out[bidx[i >> 7] * 128 + (i & 127)] = ((float*)h)[i];
}

// ============================================================================
extern "C" void kernel_launch(void* const* d_in, const int* in_sizes, int n_in,
                              void* d_out, int out_size)
{
    const int*   item_his = (const int*)d_in[0];
    const int*   seq_lens = (const int*)d_in[1];
    const float* emb      = (const float*)d_in[2];
    const float* Wg       = (const float*)d_in[3];
    const float* bg       = (const float*)d_in[4];
    const float* Wc       = (const float*)d_in[5];
    const float* bc       = (const float*)d_in[6];
    float* out = (float*)d_out;

    dim3 gA(T_ / 64, B_);   // (4, 1024)
    gru_phaseA<<<gA, 384>>>(item_his, seq_lens, emb, Wg, bg, Wc, bc);
    gru_phaseB<<<B_ / 4, 384>>>(seq_lens, Wg, Wc, out);
}

// round 4
// speedup vs baseline: 2.2211x; 1.4582x over previous
#include <cuda_runtime.h>
#include <cstdint>

#define B_ 1024
#define T_ 256
#define D_ 64
#define H_ 128

// Precomputed x-projections (pre-activation, bias included).
__device__ float g_xg[(size_t)B_ * T_ * 256];   // gate: r cols 0..127, u cols 128..255
__device__ float g_xc[(size_t)B_ * T_ * 128];   // candidate
__device__ int   g_perm[B_];                    // rows sorted by len desc

// ---- packed f32x2 helpers ----
__device__ __forceinline__ unsigned long long pack2(float lo, float hi) {
    unsigned long long r;
    asm("mov.b64 %0, {%1, %2};" : "=l"(r) : "f"(lo), "f"(hi));
    return r;
}
__device__ __forceinline__ void fma2(unsigned long long& acc,
                                     unsigned long long a,
                                     unsigned long long b) {
    asm("fma.rn.f32x2 %0, %1, %2, %0;" : "+l"(acc) : "l"(a), "l"(b));
}
__device__ __forceinline__ float sum2(unsigned long long a) {
    float lo, hi;
    asm("mov.b64 {%0, %1}, %2;" : "=f"(lo), "=f"(hi) : "l"(a));
    return lo + hi;
}
__device__ __forceinline__ float sigmoidf(float s) { return 1.f / (1.f + __expf(-s)); }
__device__ __forceinline__ float tanh_safe(float s) {
    const float sc = fminf(fmaxf(s, -15.f), 15.f);
    const float e  = __expf(2.f * sc);
    return (e - 1.f) / (e + 1.f);
}

// ============================================================================
// Sort rows by seq_len descending (counting sort, one CTA).
// ============================================================================
__global__ void sort_rows(const int* __restrict__ seq_lens) {
    __shared__ int base[T_ + 1];
    const int tid = threadIdx.x;          // 1024 threads
    if (tid <= T_) base[tid] = 0;
    __syncthreads();
    const int len = seq_lens[tid];
    atomicAdd(&base[len], 1);
    __syncthreads();
    if (tid == 0) {                        // descending prefix
        int acc = 0;
        for (int l = T_; l >= 0; l--) { int c = base[l]; base[l] = acc; acc += c; }
    }
    __syncthreads();
    const int pos = atomicAdd(&base[len], 1);
    g_perm[pos] = tid;
}

// ============================================================================
// Phase A: time-parallel x-projections. Weights in regs, x via LDS.128.
// ============================================================================
__global__ __launch_bounds__(384)
void gru_phaseA(const int* __restrict__ item_his,
                const int* __restrict__ seq_lens,
                const float* __restrict__ emb,
                const float* __restrict__ Wg,
                const float* __restrict__ bg,
                const float* __restrict__ Wc,
                const float* __restrict__ bc)
{
    const int b  = blockIdx.y;
    const int t0 = blockIdx.x * 64;
    const int len = seq_lens[b];
    if (t0 >= len) return;
    const int nt = min(64, len - t0);
    const int tid = threadIdx.x;

    __shared__ int idx_sh[64];
    __shared__ __align__(16) float x_sh[64 * 64];

    unsigned long long wp[32];
    float bias;
    if (tid < 256) {
        bias = bg[tid];
#pragma unroll
        for (int i = 0; i < 32; i++)
            wp[i] = pack2(Wg[(2 * i) * 256 + tid], Wg[(2 * i + 1) * 256 + tid]);
    } else {
        const int c = tid - 256;
        bias = bc[c];
#pragma unroll
        for (int i = 0; i < 32; i++)
            wp[i] = pack2(Wc[(2 * i) * 128 + c], Wc[(2 * i + 1) * 128 + c]);
    }

    if (tid < nt) idx_sh[tid] = item_his[b * T_ + t0 + tid];
    __syncthreads();

    {   // coalesced gather: nt embedding rows of 256B each
        const float4* e4 = (const float4*)emb;
        float4* x4 = (float4*)x_sh;
        for (int i = tid; i < nt * 16; i += 384) {
            const int r = i >> 4, q = i & 15;
            x4[r * 16 + q] = e4[(size_t)idx_sh[r] * 16 + q];
        }
    }
    __syncthreads();

    const ulonglong2* x2 = (const ulonglong2*)x_sh;
    // two rows at a time for ILP
    for (int r = 0; r < nt; r += 2) {
        const bool two = (r + 1 < nt);
        unsigned long long a0 = 0ULL, a1 = 0ULL, b0 = 0ULL, b1 = 0ULL;
#pragma unroll
        for (int i = 0; i < 16; i++) {
            ulonglong2 xx = x2[r * 16 + i];
            fma2(a0, xx.x, wp[2 * i]);
            fma2(a1, xx.y, wp[2 * i + 1]);
            if (two) {
                ulonglong2 yy = x2[(r + 1) * 16 + i];
                fma2(b0, yy.x, wp[2 * i]);
                fma2(b1, yy.y, wp[2 * i + 1]);
            }
        }
        const float acc0 = sum2(a0) + sum2(a1) + bias;
        const size_t p0 = (size_t)b * T_ + t0 + r;
        if (tid < 256) __stcs(&g_xg[p0 * 256 + tid], acc0);
        else           __stcs(&g_xc[p0 * 128 + (tid - 256)], acc0);
        if (two) {
            const float acc1 = sum2(b0) + sum2(b1) + bias;
            if (tid < 256) __stcs(&g_xg[(p0 + 1) * 256 + tid], acc1);
            else           __stcs(&g_xc[(p0 + 1) * 128 + (tid - 256)], acc1);
        }
    }
}

// ============================================================================
// Phase B: pipelined recurrence on length-sorted rows.
//   4 sorted rows/CTA (l0>=l1>=l2>=l3, all similar): A={0,1}, B={2,3}.
//   slot0: gates_A(t) | cand_B(t-1);  slot1: gates_B(t) | cand_A(t)
//   Weights register-resident; h/rh broadcast LDS.128; x prefetch depth 2.
// ============================================================================
template<int NR>
__device__ __forceinline__ void dot2(const unsigned long long* __restrict__ wp,
                                     const float* __restrict__ v0,
                                     const float* __restrict__ v1,
                                     float& s0, float& s1)
{
    const ulonglong2* p0 = (const ulonglong2*)v0;
    const ulonglong2* p1 = (const ulonglong2*)v1;
    unsigned long long a00 = 0ULL, a01 = 0ULL, a10 = 0ULL, a11 = 0ULL;
#pragma unroll
    for (int kk = 0; kk < 32; kk++) {
        ulonglong2 x0 = p0[kk];
        fma2(a00, x0.x, wp[2 * kk]);
        fma2(a01, x0.y, wp[2 * kk + 1]);
        if (NR == 2) {
            ulonglong2 x1 = p1[kk];
            fma2(a10, x1.x, wp[2 * kk]);
            fma2(a11, x1.y, wp[2 * kk + 1]);
        }
    }
    s0 = sum2(a00) + sum2(a01);
    if (NR == 2) s1 = sum2(a10) + sum2(a11);
}

__global__ __launch_bounds__(384, 1)
void gru_phaseB(const int* __restrict__ seq_lens,
                const float* __restrict__ Wg,
                const float* __restrict__ Wc,
                float* __restrict__ out)
{
    __shared__ __align__(16) float h[4][128];
    __shared__ __align__(16) float rh[4][128];
    __shared__ float uu[4][128];

    const int tid = threadIdx.x;
    const int cta = blockIdx.x;

    int bidx[4], len[4];
#pragma unroll
    for (int r = 0; r < 4; r++) {
        bidx[r] = g_perm[cta * 4 + r];                // sorted desc: l0>=l1>=l2>=l3
        len[r]  = seq_lens[bidx[r]];
    }
    const int tmax = len[0];

    const bool isGate = tid < 256;
    const int  j      = isGate ? tid : tid - 256;

    unsigned long long wp[64];
    if (isGate) {
#pragma unroll
        for (int i = 0; i < 64; i++)
            wp[i] = pack2(Wg[(64 + 2 * i) * 256 + j], Wg[(64 + 2 * i + 1) * 256 + j]);
    } else {
#pragma unroll
        for (int i = 0; i < 64; i++)
            wp[i] = pack2(Wc[(64 + 2 * i) * 128 + j], Wc[(64 + 2 * i + 1) * 128 + j]);
    }

    for (int i = tid; i < 512; i += 384) ((float*)h)[i] = 0.f;
    __syncthreads();

    // x-projection value for "loop iteration tt":
    //   gate threads: xg[row](tt)     (rows 0..3)
    //   cand threads: rows 0,1 -> xc(tt); rows 2,3 -> xc(tt-1)
    auto xval = [&](int r, int tt) -> float {
        if (isGate) {
            if (tt < len[r]) return __ldcs(&g_xg[((size_t)bidx[r] * T_ + tt) * 256 + j]);
        } else {
            const int t2 = (r < 2) ? tt : tt - 1;
            if (t2 >= 0 && t2 < len[r])
                return __ldcs(&g_xc[((size_t)bidx[r] * T_ + t2) * 128 + j]);
        }
        return 0.f;
    };

    // prefetch stages: q0 consumed at t, q1 at t+1, q2 loading for t+2
    float q0[4], q1[4], q2[4];
#pragma unroll
    for (int r = 0; r < 4; r++) { q0[r] = xval(r, 0); q1[r] = xval(r, 1); }

    for (int t = 0; t <= tmax; t++) {
#pragma unroll
        for (int r = 0; r < 4; r++) q2[r] = xval(r, t + 2);

        // ---- slot 0: gates_A(t) | cand_B(t-1) ----
        if (isGate) {
            if (t < len[0]) {
                float s0, s1;
                if (t < len[1]) dot2<2>(wp, h[0], h[1], s0, s1);
                else            dot2<1>(wp, h[0], h[1], s0, s1);
                const float g0 = sigmoidf(s0 + q0[0]);
                if (j < 128) rh[0][j] = g0 * h[0][j]; else uu[0][j - 128] = g0;
                if (t < len[1]) {
                    const float g1 = sigmoidf(s1 + q0[1]);
                    if (j < 128) rh[1][j] = g1 * h[1][j]; else uu[1][j - 128] = g1;
                }
            }
        } else {
            const int tt = t - 1;
            if (tt >= 0 && tt < len[2]) {
                float s0, s1;
                if (tt < len[3]) dot2<2>(wp, rh[2], rh[3], s0, s1);
                else             dot2<1>(wp, rh[2], rh[3], s0, s1);
                const float c0 = tanh_safe(s0 + q0[2]);
                const float u0 = uu[2][j];
                h[2][j] = u0 * h[2][j] + (1.f - u0) * c0;
                if (tt < len[3]) {
                    const float c1 = tanh_safe(s1 + q0[3]);
                    const float u1 = uu[3][j];
                    h[3][j] = u1 * h[3][j] + (1.f - u1) * c1;
                }
            }
        }
        __syncthreads();

        // ---- slot 1: gates_B(t) | cand_A(t) ----
        if (isGate) {
            if (t < len[2]) {
                float s0, s1;
                if (t < len[3]) dot2<2>(wp, h[2], h[3], s0, s1);
                else            dot2<1>(wp, h[2], h[3], s0, s1);
                const float g0 = sigmoidf(s0 + q0[2]);
                if (j < 128) rh[2][j] = g0 * h[2][j]; else uu[2][j - 128] = g0;
                if (t < len[3]) {
                    const float g1 = sigmoidf(s1 + q0[3]);
                    if (j < 128) rh[3][j] = g1 * h[3][j]; else uu[3][j - 128] = g1;
                }
            }
        } else {
            if (t < len[0]) {
                float s0, s1;
                if (t < len[1]) dot2<2>(wp, rh[0], rh[1], s0, s1);
                else            dot2<1>(wp, rh[0], rh[1], s0, s1);
                const float c0 = tanh_safe(s0 + q0[0]);
                const float u0 = uu[0][j];
                h[0][j] = u0 * h[0][j] + (1.f - u0) * c0;
                if (t < len[1]) {
                    const float c1 = tanh_safe(s1 + q0[1]);
                    const float u1 = uu[1][j];
                    h[1][j] = u1 * h[1][j] + (1.f - u1) * c1;
                }
            }
        }
        __syncthreads();

#pragma unroll
        for (int r = 0; r < 4; r++) { q0[r] = q1[r]; q1[r] = q2[r]; }
    }

    for (int i = tid; i < 512; i += 384)
        out[bidx[i >> 7] * 128 + (i & 127)] = ((float*)h)[i];
}

// ============================================================================
extern "C" void kernel_launch(void* const* d_in, const int* in_sizes, int n_in,
                              void* d_out, int out_size)
{
    const int*   item_his = (const int*)d_in[0];
    const int*   seq_lens = (const int*)d_in[1];
    const float* emb      = (const float*)d_in[2];
    const float* Wg       = (const float*)d_in[3];
    const float* bg       = (const float*)d_in[4];
    const float* Wc       = (const float*)d_in[5];
    const float* bc       = (const float*)d_in[6];
    float* out = (float*)d_out;

    sort_rows<<<1, B_>>>(seq_lens);
    dim3 gA(T_ / 64, B_);   // (4, 1024)
    gru_phaseA<<<gA, 384>>>(item_his, seq_lens, emb, Wg, bg, Wc, bc);
    gru_phaseB<<<B_ / 4, 384>>>(seq_lens, Wg, Wc, out);
}

// round 5
// speedup vs baseline: 2.3453x; 1.0559x over previous
#include <cuda_runtime.h>
#include <cstdint>

#define B_ 1024
#define T_ 256
#define D_ 64
#define H_ 128

// Precomputed x-projections (pre-activation, bias included).
__device__ float g_xg[(size_t)B_ * T_ * 256];   // gate: r cols 0..127, u cols 128..255
__device__ float g_xc[(size_t)B_ * T_ * 128];   // candidate
__device__ int   g_perm[B_];                    // rows sorted by len desc

// ---- packed f32x2 helpers ----
__device__ __forceinline__ unsigned long long pack2(float lo, float hi) {
    unsigned long long r;
    asm("mov.b64 %0, {%1, %2};" : "=l"(r) : "f"(lo), "f"(hi));
    return r;
}
__device__ __forceinline__ void fma2(unsigned long long& acc,
                                     unsigned long long a,
                                     unsigned long long b) {
    asm("fma.rn.f32x2 %0, %1, %2, %0;" : "+l"(acc) : "l"(a), "l"(b));
}
__device__ __forceinline__ float sum2(unsigned long long a) {
    float lo, hi;
    asm("mov.b64 {%0, %1}, %2;" : "=f"(lo), "=f"(hi) : "l"(a));
    return lo + hi;
}
__device__ __forceinline__ float sigmoidf(float s) { return 1.f / (1.f + __expf(-s)); }
__device__ __forceinline__ float tanh_safe(float s) {
    const float sc = fminf(fmaxf(s, -15.f), 15.f);
    const float e  = __expf(2.f * sc);
    return (e - 1.f) / (e + 1.f);
}

// named-barrier producer/consumer sync (384 = all threads in CTA)
#define BSYNC(id)   asm volatile("bar.sync %0, 384;"   :: "r"(id) : "memory")
#define BARRIVE(id) asm volatile("bar.arrive %0, 384;" :: "r"(id) : "memory")

// ============================================================================
// Sort rows by seq_len descending (counting sort, one CTA).
// ============================================================================
__global__ void sort_rows(const int* __restrict__ seq_lens) {
    __shared__ int base[T_ + 1];
    const int tid = threadIdx.x;          // 1024 threads
    if (tid <= T_) base[tid] = 0;
    __syncthreads();
    const int len = seq_lens[tid];
    atomicAdd(&base[len], 1);
    __syncthreads();
    if (tid == 0) {                        // descending prefix
        int acc = 0;
        for (int l = T_; l >= 0; l--) { int c = base[l]; base[l] = acc; acc += c; }
    }
    __syncthreads();
    const int pos = atomicAdd(&base[len], 1);
    g_perm[pos] = tid;
}

// ============================================================================
// Phase A: time-parallel x-projections. Weights in regs, x via LDS.128.
// ============================================================================
__global__ __launch_bounds__(384)
void gru_phaseA(const int* __restrict__ item_his,
                const int* __restrict__ seq_lens,
                const float* __restrict__ emb,
                const float* __restrict__ Wg,
                const float* __restrict__ bg,
                const float* __restrict__ Wc,
                const float* __restrict__ bc)
{
    const int b  = blockIdx.y;
    const int t0 = blockIdx.x * 64;
    const int len = seq_lens[b];
    if (t0 >= len) return;
    const int nt = min(64, len - t0);
    const int tid = threadIdx.x;

    __shared__ int idx_sh[64];
    __shared__ __align__(16) float x_sh[64 * 64];

    unsigned long long wp[32];
    float bias;
    if (tid < 256) {
        bias = bg[tid];
#pragma unroll
        for (int i = 0; i < 32; i++)
            wp[i] = pack2(Wg[(2 * i) * 256 + tid], Wg[(2 * i + 1) * 256 + tid]);
    } else {
        const int c = tid - 256;
        bias = bc[c];
#pragma unroll
        for (int i = 0; i < 32; i++)
            wp[i] = pack2(Wc[(2 * i) * 128 + c], Wc[(2 * i + 1) * 128 + c]);
    }

    if (tid < nt) idx_sh[tid] = item_his[b * T_ + t0 + tid];
    __syncthreads();

    {   // coalesced gather: nt embedding rows of 256B each
        const float4* e4 = (const float4*)emb;
        float4* x4 = (float4*)x_sh;
        for (int i = tid; i < nt * 16; i += 384) {
            const int r = i >> 4, q = i & 15;
            x4[r * 16 + q] = e4[(size_t)idx_sh[r] * 16 + q];
        }
    }
    __syncthreads();

    const ulonglong2* x2 = (const ulonglong2*)x_sh;
    for (int r = 0; r < nt; r += 2) {
        const bool two = (r + 1 < nt);
        unsigned long long a0 = 0ULL, a1 = 0ULL, b0 = 0ULL, b1 = 0ULL;
#pragma unroll
        for (int i = 0; i < 16; i++) {
            ulonglong2 xx = x2[r * 16 + i];
            fma2(a0, xx.x, wp[2 * i]);
            fma2(a1, xx.y, wp[2 * i + 1]);
            if (two) {
                ulonglong2 yy = x2[(r + 1) * 16 + i];
                fma2(b0, yy.x, wp[2 * i]);
                fma2(b1, yy.y, wp[2 * i + 1]);
            }
        }
        const float acc0 = sum2(a0) + sum2(a1) + bias;
        const size_t p0 = (size_t)b * T_ + t0 + r;
        if (tid < 256) __stcs(&g_xg[p0 * 256 + tid], acc0);
        else           __stcs(&g_xc[p0 * 128 + (tid - 256)], acc0);
        if (two) {
            const float acc1 = sum2(b0) + sum2(b1) + bias;
            if (tid < 256) __stcs(&g_xg[(p0 + 1) * 256 + tid], acc1);
            else           __stcs(&g_xc[(p0 + 1) * 128 + (tid - 256)], acc1);
        }
    }
}

// ============================================================================
// Phase B: decoupled producer/consumer recurrence on length-sorted rows.
//   4 sorted rows/CTA: A={0,1}, B={2,3}.
//   gate warps (256 thr): sync(1) G_A(t) arrive(3) | sync(2) G_B(t) arrive(4)
//   cand warps (128 thr): sync(3) C_A(t) arrive(1) | sync(4) C_B(t) arrive(2)
//   Weights register-resident; h/rh broadcast LDS.128; x prefetch depth 2.
// ============================================================================
template<int NR>
__device__ __forceinline__ void dot2(const unsigned long long* __restrict__ wp,
                                     const float* __restrict__ v0,
                                     const float* __restrict__ v1,
                                     float& s0, float& s1)
{
    const ulonglong2* p0 = (const ulonglong2*)v0;
    const ulonglong2* p1 = (const ulonglong2*)v1;
    unsigned long long a00 = 0ULL, a01 = 0ULL, a10 = 0ULL, a11 = 0ULL;
#pragma unroll
    for (int kk = 0; kk < 32; kk++) {
        ulonglong2 x0 = p0[kk];
        fma2(a00, x0.x, wp[2 * kk]);
        fma2(a01, x0.y, wp[2 * kk + 1]);
        if (NR == 2) {
            ulonglong2 x1 = p1[kk];
            fma2(a10, x1.x, wp[2 * kk]);
            fma2(a11, x1.y, wp[2 * kk + 1]);
        }
    }
    s0 = sum2(a00) + sum2(a01);
    if (NR == 2) s1 = sum2(a10) + sum2(a11);
}

__global__ __launch_bounds__(384, 1)
void gru_phaseB(const int* __restrict__ seq_lens,
                const float* __restrict__ Wg,
                const float* __restrict__ Wc,
                float* __restrict__ out)
{
    __shared__ __align__(16) float h[4][128];
    __shared__ __align__(16) float rh[4][128];
    __shared__ float uu[4][128];

    const int tid = threadIdx.x;
    const int cta = blockIdx.x;

    int bidx[4], len[4];
#pragma unroll
    for (int r = 0; r < 4; r++) {
        bidx[r] = g_perm[cta * 4 + r];                // sorted desc: l0>=l1>=l2>=l3
        len[r]  = seq_lens[bidx[r]];
    }
    const int tmax = len[0];
    if (tmax == 0) {
        for (int i = tid; i < 512; i += 384)
            out[bidx[i >> 7] * 128 + (i & 127)] = 0.f;
        return;
    }

    const bool isGate = tid < 256;
    const int  j      = isGate ? tid : tid - 256;

    unsigned long long wp[64];
    if (isGate) {
#pragma unroll
        for (int i = 0; i < 64; i++)
            wp[i] = pack2(Wg[(64 + 2 * i) * 256 + j], Wg[(64 + 2 * i + 1) * 256 + j]);
    } else {
#pragma unroll
        for (int i = 0; i < 64; i++)
            wp[i] = pack2(Wc[(64 + 2 * i) * 128 + j], Wc[(64 + 2 * i + 1) * 128 + j]);
    }

    for (int i = tid; i < 512; i += 384) ((float*)h)[i] = 0.f;
    __syncthreads();

    // x prefetch (depth 2): gate threads load xg(r,t), cand threads xc(r,t)
    auto xval = [&](int r, int tt) -> float {
        if (tt < len[r]) {
            if (isGate) return __ldcs(&g_xg[((size_t)bidx[r] * T_ + tt) * 256 + j]);
            else        return __ldcs(&g_xc[((size_t)bidx[r] * T_ + tt) * 128 + j]);
        }
        return 0.f;
    };
    float q0[4], q1[4], q2[4];
#pragma unroll
    for (int r = 0; r < 4; r++) { q0[r] = xval(r, 0); q1[r] = xval(r, 1); }

    // cand pre-arms the h-ready barriers (h zeroed + synced above)
    if (!isGate) { BARRIVE(1); BARRIVE(2); }

    for (int t = 0; t < tmax; t++) {
#pragma unroll
        for (int r = 0; r < 4; r++) q2[r] = xval(r, t + 2);

        if (isGate) {
            // ---- G_A(t): rows 0,1 ----
            BSYNC(1);
            {
                float s0, s1;
                if (t < len[1]) dot2<2>(wp, h[0], h[1], s0, s1);
                else            dot2<1>(wp, h[0], h[1], s0, s1);
                const float g0 = sigmoidf(s0 + q0[0]);
                if (j < 128) rh[0][j] = g0 * h[0][j]; else uu[0][j - 128] = g0;
                if (t < len[1]) {
                    const float g1 = sigmoidf(s1 + q0[1]);
                    if (j < 128) rh[1][j] = g1 * h[1][j]; else uu[1][j - 128] = g1;
                }
            }
            BARRIVE(3);
            // ---- G_B(t): rows 2,3 ----
            BSYNC(2);
            if (t < len[2]) {
                float s0, s1;
                if (t < len[3]) dot2<2>(wp, h[2], h[3], s0, s1);
                else            dot2<1>(wp, h[2], h[3], s0, s1);
                const float g0 = sigmoidf(s0 + q0[2]);
                if (j < 128) rh[2][j] = g0 * h[2][j]; else uu[2][j - 128] = g0;
                if (t < len[3]) {
                    const float g1 = sigmoidf(s1 + q0[3]);
                    if (j < 128) rh[3][j] = g1 * h[3][j]; else uu[3][j - 128] = g1;
                }
            }
            BARRIVE(4);
        } else {
            // ---- C_A(t): rows 0,1 ----
            BSYNC(3);
            {
                float s0, s1;
                if (t < len[1]) dot2<2>(wp, rh[0], rh[1], s0, s1);
                else            dot2<1>(wp, rh[0], rh[1], s0, s1);
                const float c0 = tanh_safe(s0 + q0[0]);
                const float u0 = uu[0][j];
                h[0][j] = u0 * h[0][j] + (1.f - u0) * c0;
                if (t < len[1]) {
                    const float c1 = tanh_safe(s1 + q0[1]);
                    const float u1 = uu[1][j];
                    h[1][j] = u1 * h[1][j] + (1.f - u1) * c1;
                }
            }
            if (t + 1 < tmax) BARRIVE(1);
            // ---- C_B(t): rows 2,3 ----
            BSYNC(4);
            if (t < len[2]) {
                float s0, s1;
                if (t < len[3]) dot2<2>(wp, rh[2], rh[3], s0, s1);
                else            dot2<1>(wp, rh[2], rh[3], s0, s1);
                const float c0 = tanh_safe(s0 + q0[2]);
                const float u0 = uu[2][j];
                h[2][j] = u0 * h[2][j] + (1.f - u0) * c0;
                if (t < len[3]) {
                    const float c1 = tanh_safe(s1 + q0[3]);
                    const float u1 = uu[3][j];
                    h[3][j] = u1 * h[3][j] + (1.f - u1) * c1;
                }
            }
            if (t + 1 < tmax) BARRIVE(2);
        }

#pragma unroll
        for (int r = 0; r < 4; r++) { q0[r] = q1[r]; q1[r] = q2[r]; }
    }

    __syncthreads();
    for (int i = tid; i < 512; i += 384)
        out[bidx[i >> 7] * 128 + (i & 127)] = ((float*)h)[i];
}

// ============================================================================
extern "C" void kernel_launch(void* const* d_in, const int* in_sizes, int n_in,
                              void* d_out, int out_size)
{
    const int*   item_his = (const int*)d_in[0];
    const int*   seq_lens = (const int*)d_in[1];
    const float* emb      = (const float*)d_in[2];
    const float* Wg       = (const float*)d_in[3];
    const float* bg       = (const float*)d_in[4];
    const float* Wc       = (const float*)d_in[5];
    const float* bc       = (const float*)d_in[6];
    float* out = (float*)d_out;

    sort_rows<<<1, B_>>>(seq_lens);
    dim3 gA(T_ / 64, B_);   // (4, 1024)
    gru_phaseA<<<gA, 384>>>(item_his, seq_lens, emb, Wg, bg, Wc, bc);
    gru_phaseB<<<B_ / 4, 384>>>(seq_lens, Wg, Wc, out);
}